// round 1
// baseline (speedup 1.0000x reference)
#include <cuda_runtime.h>
#include <math.h>

#define S 2048
#define DMODEL 512
#define NH 8
#define DKH 64
#define WIN 64
#define NEGV -1000000000.0f

#define QS_STR 68
#define KS_STR 132
#define VS_STR 68
#define PS_STR 68

// Scratch (allocation-free rule: __device__ globals)
__device__ float g_Q[S * DMODEL];
__device__ float g_K[S * DMODEL];
__device__ float g_V[S * DMODEL];
__device__ float g_AO[S * DMODEL];

// C[M,N] = A[M,K] @ Wt[N,K]^T (+ bias[n] if bias != nullptr)
// 64x64 block tile, BK=32, 256 threads, 4x4 per-thread register tile.
__global__ void __launch_bounds__(256) gemm_xt(
    const float* __restrict__ A, const float* __restrict__ Wt,
    const float* __restrict__ bias, float* __restrict__ C,
    int M, int N, int K)
{
    __shared__ __align__(16) float As[32][68];  // [k][m], padded
    __shared__ __align__(16) float Bs[32][68];  // [k][n], padded
    const int tid = threadIdx.x;
    const int tx = tid & 15, ty = tid >> 4;
    const int m_base = blockIdx.y * 64;
    const int n_base = blockIdx.x * 64;

    float acc[4][4] = {};

    for (int k0 = 0; k0 < K; k0 += 32) {
        #pragma unroll
        for (int r = 0; r < 2; r++) {
            int idx = tid + r * 256;          // 0..511 float4 slots
            int row = idx >> 3;               // 0..63
            int c4  = (idx & 7) << 2;         // 0,4,...,28
            float4 va = *(const float4*)(A + (size_t)(m_base + row) * K + k0 + c4);
            As[c4 + 0][row] = va.x; As[c4 + 1][row] = va.y;
            As[c4 + 2][row] = va.z; As[c4 + 3][row] = va.w;
            float4 vb = *(const float4*)(Wt + (size_t)(n_base + row) * K + k0 + c4);
            Bs[c4 + 0][row] = vb.x; Bs[c4 + 1][row] = vb.y;
            Bs[c4 + 2][row] = vb.z; Bs[c4 + 3][row] = vb.w;
        }
        __syncthreads();
        #pragma unroll
        for (int k = 0; k < 32; k++) {
            float4 a = *(const float4*)&As[k][ty * 4];
            float4 b = *(const float4*)&Bs[k][tx * 4];
            float av[4] = {a.x, a.y, a.z, a.w};
            float bv[4] = {b.x, b.y, b.z, b.w};
            #pragma unroll
            for (int i = 0; i < 4; i++)
                #pragma unroll
                for (int j = 0; j < 4; j++)
                    acc[i][j] = fmaf(av[i], bv[j], acc[i][j]);
        }
        __syncthreads();
    }

    #pragma unroll
    for (int i = 0; i < 4; i++) {
        int m = m_base + ty * 4 + i;
        int n = n_base + tx * 4;
        float4 o = {acc[i][0], acc[i][1], acc[i][2], acc[i][3]};
        if (bias) {
            float4 bb = *(const float4*)(bias + n);
            o.x += bb.x; o.y += bb.y; o.z += bb.z; o.w += bb.w;
        }
        *(float4*)(C + (size_t)m * N + n) = o;
    }
}

// One block = (64-query tile, head). Key window for the tile = 128 keys.
// Dense 64x128 scores -> mask+bias -> softmax -> PV -> O, plus attn_w gather.
__global__ void __launch_bounds__(256) local_attn(
    const float* __restrict__ Q, const float* __restrict__ K,
    const float* __restrict__ V, float* __restrict__ O,
    float* __restrict__ attn_w)
{
    extern __shared__ __align__(16) float sm[];
    float* Qs = sm;                        // [64][QS_STR]  Qs[d][qi]
    float* Ks = Qs + 64 * QS_STR;          // [64][KS_STR]  Ks[d][kk]
    float* Vs = Ks + 64 * KS_STR;          // [128][VS_STR] Vs[kk][dk]
    float* Ps = Vs + 128 * VS_STR;         // [128][PS_STR] Ps[kk][qi]

    const int h  = blockIdx.y;
    const int i0 = blockIdx.x * 64;
    const int tid = threadIdx.x;

    // Load Q tile (transposed, padded)
    for (int idx = tid; idx < 64 * 64; idx += 256) {
        int qi = idx >> 6, d = idx & 63;
        Qs[d * QS_STR + qi] = Q[(size_t)(i0 + qi) * DMODEL + h * DKH + d];
    }
    // Load 128-key K (transposed) and V (natural) tiles; clamp j<0 (masked later)
    for (int idx = tid; idx < 128 * 64; idx += 256) {
        int kk = idx >> 6, d = idx & 63;
        int j = i0 - 64 + kk;
        int jc = j < 0 ? 0 : j;
        Ks[d * KS_STR + kk] = K[(size_t)jc * DMODEL + h * DKH + d];
        Vs[kk * VS_STR + d] = V[(size_t)jc * DMODEL + h * DKH + d];
    }
    __syncthreads();

    const int tx = tid & 15, ty = tid >> 4;
    const int qi0 = ty * 4, kk0 = tx * 8;

    // Scores: 4 qi x 8 kk per thread
    float sc[4][8] = {};
    #pragma unroll 8
    for (int d = 0; d < 64; d++) {
        float4 a  = *(const float4*)&Qs[d * QS_STR + qi0];
        float4 b0 = *(const float4*)&Ks[d * KS_STR + kk0];
        float4 b1 = *(const float4*)&Ks[d * KS_STR + kk0 + 4];
        float av[4] = {a.x, a.y, a.z, a.w};
        float bv[8] = {b0.x, b0.y, b0.z, b0.w, b1.x, b1.y, b1.z, b1.w};
        #pragma unroll
        for (int i = 0; i < 4; i++)
            #pragma unroll
            for (int j = 0; j < 8; j++)
                sc[i][j] = fmaf(av[i], bv[j], sc[i][j]);
    }
    // Scale + decay bias + mask, write transposed to Ps[kk][qi]
    #pragma unroll
    for (int i = 0; i < 4; i++) {
        #pragma unroll
        for (int j = 0; j < 8; j++) {
            int qi = qi0 + i, kk = kk0 + j;
            int r  = kk - qi;                 // rel index 0..64 valid
            int jg = i0 - 64 + kk;            // absolute key index
            float val = NEGV;
            if (r >= 0 && r <= WIN && jg >= 0)
                val = sc[i][j] * 0.125f + 0.1f * expf(-0.1f * (float)(WIN - r));
            Ps[kk * PS_STR + qi] = val;
        }
    }
    __syncthreads();

    // Softmax over kk for each row qi (one warp -> 8 rows, 4 entries/lane)
    {
        const int warp = tid >> 5, lane = tid & 31;
        for (int rr = 0; rr < 8; rr++) {
            int qi = warp * 8 + rr;
            float v[4];
            float mx = -3.4e38f;
            #pragma unroll
            for (int t = 0; t < 4; t++) {
                v[t] = Ps[(lane + t * 32) * PS_STR + qi];
                mx = fmaxf(mx, v[t]);
            }
            #pragma unroll
            for (int o = 16; o > 0; o >>= 1)
                mx = fmaxf(mx, __shfl_xor_sync(0xffffffffu, mx, o));
            float sum = 0.f;
            #pragma unroll
            for (int t = 0; t < 4; t++) { v[t] = expf(v[t] - mx); sum += v[t]; }
            #pragma unroll
            for (int o = 16; o > 0; o >>= 1)
                sum += __shfl_xor_sync(0xffffffffu, sum, o);
            float inv = 1.0f / sum;
            #pragma unroll
            for (int t = 0; t < 4; t++)
                Ps[(lane + t * 32) * PS_STR + qi] = v[t] * inv;
        }
    }
    __syncthreads();

    // attn_w: full 128-slot rows written (zeros where invalid -> covers poison)
    // stored rows: i < 64  -> attn_w[i][slot] = probs(key j = slot), slot <= i
    //              i >= S-64 -> attn_w[i][slot] = probs(r = slot),   slot <= 64
    for (int idx = tid; idx < 64 * 128; idx += 256) {
        int qi = idx >> 7, slot = idx & 127;
        int i = i0 + qi;
        float val = 0.0f;
        if (i < WIN) {
            if (slot <= qi) val = Ps[(slot + 64) * PS_STR + qi];
        } else if (i >= S - WIN) {
            if (slot <= WIN) val = Ps[(qi + slot) * PS_STR + qi];
        }
        attn_w[((size_t)h * S + i) * 128 + slot] = val;
    }

    // PV: out[qi][dk] = sum_kk Ps[kk][qi] * Vs[kk][dk]; 4 qi x 4 dk per thread
    const int dk0 = tx * 4;
    float acc[4][4] = {};
    #pragma unroll 4
    for (int kk = 0; kk < 128; kk++) {
        float4 p  = *(const float4*)&Ps[kk * PS_STR + qi0];
        float4 vv = *(const float4*)&Vs[kk * VS_STR + dk0];
        float pv[4] = {p.x, p.y, p.z, p.w};
        float vb[4] = {vv.x, vv.y, vv.z, vv.w};
        #pragma unroll
        for (int i = 0; i < 4; i++)
            #pragma unroll
            for (int j = 0; j < 4; j++)
                acc[i][j] = fmaf(pv[i], vb[j], acc[i][j]);
    }
    #pragma unroll
    for (int i = 0; i < 4; i++) {
        float4 o = {acc[i][0], acc[i][1], acc[i][2], acc[i][3]};
        *(float4*)(O + (size_t)(i0 + qi0 + i) * DMODEL + h * DKH + dk0) = o;
    }
}

extern "C" void kernel_launch(void* const* d_in, const int* in_sizes, int n_in,
                              void* d_out, int out_size) {
    const float* q  = (const float*)d_in[0];
    const float* k  = (const float*)d_in[1];
    const float* v  = (const float*)d_in[2];
    const float* Wq = (const float*)d_in[3];
    const float* Wk = (const float*)d_in[4];
    const float* Wv = (const float*)d_in[5];
    const float* Wo = (const float*)d_in[6];
    const float* bo = (const float*)d_in[7];

    float* out    = (float*)d_out;                 // (1,2048,512)
    float* attn_w = out + (size_t)S * DMODEL;      // (1,8,2048,128)

    float *pQ, *pK, *pV, *pAO;
    cudaGetSymbolAddress((void**)&pQ,  g_Q);
    cudaGetSymbolAddress((void**)&pK,  g_K);
    cudaGetSymbolAddress((void**)&pV,  g_V);
    cudaGetSymbolAddress((void**)&pAO, g_AO);

    const int SMEM = (64 * QS_STR + 64 * KS_STR + 128 * VS_STR + 128 * PS_STR)
                     * (int)sizeof(float);
    cudaFuncSetAttribute(local_attn, cudaFuncAttributeMaxDynamicSharedMemorySize, SMEM);

    dim3 gg(DMODEL / 64, S / 64);
    gemm_xt<<<gg, 256>>>(q, Wq, nullptr, pQ, S, DMODEL, DMODEL);
    gemm_xt<<<gg, 256>>>(k, Wk, nullptr, pK, S, DMODEL, DMODEL);
    gemm_xt<<<gg, 256>>>(v, Wv, nullptr, pV, S, DMODEL, DMODEL);
    local_attn<<<dim3(S / 64, NH), 256, SMEM>>>(pQ, pK, pV, pAO, attn_w);
    gemm_xt<<<gg, 256>>>(pAO, Wo, bo, out, S, DMODEL, DMODEL);
}

// round 4
// speedup vs baseline: 1.9490x; 1.9490x over previous
#include <cuda_runtime.h>
#include <cuda_bf16.h>
#include <cstdint>
#include <math.h>

#define S 2048
#define DMODEL 512
#define NH 8
#define DKH 64
#define WIN 64
#define NEGV -1000000000.0f
#define SD (S*DMODEL)
#define DD (DMODEL*DMODEL)

#define QS_STR 68
#define KS_STR 132
#define VS_STR 68
#define PS_STR 68

#define LDA 40

typedef unsigned int u32;

// ---------------- device scratch (allocation-free rule) ----------------
__device__ __nv_bfloat16 g_xh[3*SD];
__device__ __nv_bfloat16 g_xl[3*SD];
__device__ __nv_bfloat16 g_Wh[4*DD];
__device__ __nv_bfloat16 g_Wl[4*DD];
__device__ float g_QKV[3*SD];
__device__ __nv_bfloat16 g_AOh[SD];
__device__ __nv_bfloat16 g_AOl[SD];

// ---------------- fp32 -> bf16 hi/lo split ----------------
__global__ void __launch_bounds__(256) convert_split(
    const float* __restrict__ q, const float* __restrict__ k, const float* __restrict__ v,
    const float* __restrict__ Wq, const float* __restrict__ Wk,
    const float* __restrict__ Wv, const float* __restrict__ Wo)
{
    const int SD4 = SD/4;
    const int DD4 = DD/4;
    int idx = blockIdx.x * 256 + threadIdx.x;
    const float* src;
    __nv_bfloat16* dh;
    __nv_bfloat16* dl;
    if (idx < 3*SD4) {
        int r = idx / SD4;
        size_t e = (size_t)(idx - r*SD4) * 4;
        src = (r == 0 ? q : (r == 1 ? k : v)) + e;
        dh = g_xh + (size_t)r*SD + e;
        dl = g_xl + (size_t)r*SD + e;
    } else {
        int j = idx - 3*SD4;
        int r = j / DD4;
        size_t e = (size_t)(j - r*DD4) * 4;
        src = (r == 0 ? Wq : (r == 1 ? Wk : (r == 2 ? Wv : Wo))) + e;
        dh = g_Wh + (size_t)r*DD + e;
        dl = g_Wl + (size_t)r*DD + e;
    }
    float4 f = *(const float4*)src;
    __nv_bfloat16 h0 = __float2bfloat16(f.x);
    __nv_bfloat16 h1 = __float2bfloat16(f.y);
    __nv_bfloat16 h2 = __float2bfloat16(f.z);
    __nv_bfloat16 h3 = __float2bfloat16(f.w);
    __nv_bfloat16 l0 = __float2bfloat16(f.x - __bfloat162float(h0));
    __nv_bfloat16 l1 = __float2bfloat16(f.y - __bfloat162float(h1));
    __nv_bfloat16 l2 = __float2bfloat16(f.z - __bfloat162float(h2));
    __nv_bfloat16 l3 = __float2bfloat16(f.w - __bfloat162float(h3));
    *(__nv_bfloat162*)(dh)     = __halves2bfloat162(h0, h1);
    *(__nv_bfloat162*)(dh + 2) = __halves2bfloat162(h2, h3);
    *(__nv_bfloat162*)(dl)     = __halves2bfloat162(l0, l1);
    *(__nv_bfloat162*)(dl + 2) = __halves2bfloat162(l2, l3);
}

// ---------------- tensor-core GEMM helpers ----------------
__device__ __forceinline__ void ldsm4(u32* r, u32 a) {
    asm volatile("ldmatrix.sync.aligned.m8n8.x4.shared.b16 {%0,%1,%2,%3}, [%4];"
        : "=r"(r[0]), "=r"(r[1]), "=r"(r[2]), "=r"(r[3]) : "r"(a));
}
__device__ __forceinline__ void mma_bf16(float* c, const u32* a, const u32* b) {
    asm volatile("mma.sync.aligned.m16n8k16.row.col.f32.bf16.bf16.f32 "
        "{%0,%1,%2,%3},{%4,%5,%6,%7},{%8,%9},{%0,%1,%2,%3};"
        : "+f"(c[0]), "+f"(c[1]), "+f"(c[2]), "+f"(c[3])
        : "r"(a[0]), "r"(a[1]), "r"(a[2]), "r"(a[3]), "r"(b[0]), "r"(b[1]));
}

// C[M,N] = A[M,K] @ W[N,K]^T (+bias). Split-bf16 3-term. Tile 128x64, BK=32.
__global__ void __launch_bounds__(256) gemm128x64(
    const __nv_bfloat16* __restrict__ Ah_, const __nv_bfloat16* __restrict__ Al_,
    const __nv_bfloat16* __restrict__ Wh_, const __nv_bfloat16* __restrict__ Wl_,
    float* __restrict__ C, const float* __restrict__ bias)
{
    __shared__ __align__(16) __nv_bfloat16 sAh[128*LDA];
    __shared__ __align__(16) __nv_bfloat16 sAl[128*LDA];
    __shared__ __align__(16) __nv_bfloat16 sWh[64*LDA];
    __shared__ __align__(16) __nv_bfloat16 sWl[64*LDA];

    const size_t za = (size_t)blockIdx.z * SD;
    const size_t zw = (size_t)blockIdx.z * DD;
    const int tid = threadIdx.x;
    const int m_base = blockIdx.y * 128;
    const int n_base = blockIdx.x * 64;

    const int a_row = tid >> 2;
    const int a_col = (tid & 3) * 8;

    const int lane = tid & 31;
    const int wid = tid >> 5;
    const int warp_m = wid >> 1;
    const int warp_n = wid & 1;
    const int lrow = (lane & 7) + ((lane >> 3) & 1) * 8;
    const int lcol = (lane >> 4) * 8;

    const u32 bAh = (u32)__cvta_generic_to_shared(sAh);
    const u32 bAl = (u32)__cvta_generic_to_shared(sAl);
    const u32 bWh = (u32)__cvta_generic_to_shared(sWh);
    const u32 bWl = (u32)__cvta_generic_to_shared(sWl);

    const __nv_bfloat16* gA  = Ah_ + za + (size_t)(m_base + a_row) * DMODEL + a_col;
    const __nv_bfloat16* gL  = Al_ + za + (size_t)(m_base + a_row) * DMODEL + a_col;
    const __nv_bfloat16* gW  = Wh_ + zw + (size_t)(n_base + a_row) * DMODEL + a_col;
    const __nv_bfloat16* gWl = Wl_ + zw + (size_t)(n_base + a_row) * DMODEL + a_col;
    float* Cz = C + za;

    float acc[2][4][4];
    #pragma unroll
    for (int mi = 0; mi < 2; mi++) {
        #pragma unroll
        for (int ni = 0; ni < 4; ni++) {
            #pragma unroll
            for (int t = 0; t < 4; t++) {
                acc[mi][ni][t] = 0.0f;
            }
        }
    }

    uint4 pA0 = *(const uint4*)(gA);
    uint4 pA1 = *(const uint4*)(gA + 64 * DMODEL);
    uint4 pL0 = *(const uint4*)(gL);
    uint4 pL1 = *(const uint4*)(gL + 64 * DMODEL);
    uint4 pW0 = *(const uint4*)(gW);
    uint4 pW1 = *(const uint4*)(gWl);

    for (int s = 0; s < 16; s++) {
        *(uint4*)&sAh[a_row * LDA + a_col]        = pA0;
        *(uint4*)&sAh[(a_row + 64) * LDA + a_col] = pA1;
        *(uint4*)&sAl[a_row * LDA + a_col]        = pL0;
        *(uint4*)&sAl[(a_row + 64) * LDA + a_col] = pL1;
        *(uint4*)&sWh[a_row * LDA + a_col]        = pW0;
        *(uint4*)&sWl[a_row * LDA + a_col]        = pW1;
        __syncthreads();

        if (s < 15) {
            int k0 = (s + 1) * 32;
            pA0 = *(const uint4*)(gA + k0);
            pA1 = *(const uint4*)(gA + k0 + 64 * DMODEL);
            pL0 = *(const uint4*)(gL + k0);
            pL1 = *(const uint4*)(gL + k0 + 64 * DMODEL);
            pW0 = *(const uint4*)(gW + k0);
            pW1 = *(const uint4*)(gWl + k0);
        }

        #pragma unroll
        for (int kb = 0; kb < 32; kb += 16) {
            u32 ah[2][4];
            u32 al[2][4];
            u32 bh[4][2];
            u32 bl[4][2];
            #pragma unroll
            for (int mi = 0; mi < 2; mi++) {
                u32 off = (u32)(((warp_m * 32 + mi * 16 + lrow) * LDA + kb + lcol) * 2);
                ldsm4(ah[mi], bAh + off);
                ldsm4(al[mi], bAl + off);
            }
            #pragma unroll
            for (int g2 = 0; g2 < 2; g2++) {
                u32 off = (u32)(((warp_n * 32 + g2 * 16 + lrow) * LDA + kb + lcol) * 2);
                u32 r0[4];
                ldsm4(r0, bWh + off);
                bh[g2*2][0]   = r0[0];
                bh[g2*2+1][0] = r0[1];
                bh[g2*2][1]   = r0[2];
                bh[g2*2+1][1] = r0[3];
                u32 r1[4];
                ldsm4(r1, bWl + off);
                bl[g2*2][0]   = r1[0];
                bl[g2*2+1][0] = r1[1];
                bl[g2*2][1]   = r1[2];
                bl[g2*2+1][1] = r1[3];
            }
            #pragma unroll
            for (int mi = 0; mi < 2; mi++) {
                #pragma unroll
                for (int ni = 0; ni < 4; ni++) {
                    mma_bf16(acc[mi][ni], ah[mi], bh[ni]);
                    mma_bf16(acc[mi][ni], ah[mi], bl[ni]);
                    mma_bf16(acc[mi][ni], al[mi], bh[ni]);
                }
            }
        }
        __syncthreads();
    }

    const int qr = lane >> 2;
    const int qc = (lane & 3) * 2;
    #pragma unroll
    for (int mi = 0; mi < 2; mi++) {
        int m0 = m_base + warp_m * 32 + mi * 16 + qr;
        #pragma unroll
        for (int ni = 0; ni < 4; ni++) {
            int n = n_base + warp_n * 32 + ni * 8 + qc;
            float b0 = 0.0f;
            float b1 = 0.0f;
            if (bias) {
                b0 = bias[n];
                b1 = bias[n + 1];
            }
            float2 v0 = make_float2(acc[mi][ni][0] + b0, acc[mi][ni][1] + b1);
            float2 v1 = make_float2(acc[mi][ni][2] + b0, acc[mi][ni][3] + b1);
            *(float2*)(Cz + (size_t)m0 * DMODEL + n) = v0;
            *(float2*)(Cz + (size_t)(m0 + 8) * DMODEL + n) = v1;
        }
    }
}

// ---------------- windowed attention ----------------
__global__ void __launch_bounds__(256) local_attn(
    const float* __restrict__ Q, const float* __restrict__ K,
    const float* __restrict__ V, float* __restrict__ attn_w)
{
    extern __shared__ __align__(16) float sm[];
    float* Qs = sm;
    float* Ks = sm + 64*QS_STR;
    float* Vs = sm + 64*QS_STR + 64*KS_STR;
    float* bias_s = Vs + 128*VS_STR;
    float* Ps = sm;   // aliases Qs+Ks after scores move to registers

    const int h  = blockIdx.y;
    const int i0 = blockIdx.x * 64;
    const int tid = threadIdx.x;

    if (tid <= WIN) {
        bias_s[tid] = 0.1f * expf(-0.1f * (float)(WIN - tid));
    }

    for (int idx = tid; idx < 64 * 64; idx += 256) {
        int qi = idx >> 6;
        int d  = idx & 63;
        Qs[d * QS_STR + qi] = Q[(size_t)(i0 + qi) * DMODEL + h * DKH + d];
    }
    for (int idx = tid; idx < 128 * 64; idx += 256) {
        int kk = idx >> 6;
        int d  = idx & 63;
        int j = i0 - 64 + kk;
        int jc = (j < 0) ? 0 : j;
        Ks[d * KS_STR + kk] = K[(size_t)jc * DMODEL + h * DKH + d];
        Vs[kk * VS_STR + d] = V[(size_t)jc * DMODEL + h * DKH + d];
    }
    __syncthreads();

    const int tx = tid & 15;
    const int ty = tid >> 4;
    const int qi0 = ty * 4;
    const int kk0 = tx * 8;

    float sc[4][8];
    #pragma unroll
    for (int i = 0; i < 4; i++) {
        #pragma unroll
        for (int j = 0; j < 8; j++) {
            sc[i][j] = 0.0f;
        }
    }
    #pragma unroll 8
    for (int d = 0; d < 64; d++) {
        float4 a  = *(const float4*)&Qs[d * QS_STR + qi0];
        float4 b0 = *(const float4*)&Ks[d * KS_STR + kk0];
        float4 b1 = *(const float4*)&Ks[d * KS_STR + kk0 + 4];
        float av[4] = {a.x, a.y, a.z, a.w};
        float bv[8] = {b0.x, b0.y, b0.z, b0.w, b1.x, b1.y, b1.z, b1.w};
        #pragma unroll
        for (int i = 0; i < 4; i++) {
            #pragma unroll
            for (int j = 0; j < 8; j++) {
                sc[i][j] = fmaf(av[i], bv[j], sc[i][j]);
            }
        }
    }
    __syncthreads();   // scores in regs; safe to overwrite Qs/Ks with Ps

    #pragma unroll
    for (int i = 0; i < 4; i++) {
        #pragma unroll
        for (int j = 0; j < 8; j++) {
            int qi = qi0 + i;
            int kk = kk0 + j;
            int r  = kk - qi;
            int jg = i0 - 64 + kk;
            float val = NEGV;
            if (r >= 0 && r <= WIN && jg >= 0) {
                val = sc[i][j] * 0.125f + bias_s[r];
            }
            Ps[kk * PS_STR + qi] = val;
        }
    }
    __syncthreads();

    {
        const int warp = tid >> 5;
        const int lane = tid & 31;
        for (int rr = 0; rr < 8; rr++) {
            int qi = warp * 8 + rr;
            float v[4];
            float mx = -3.4e38f;
            #pragma unroll
            for (int t = 0; t < 4; t++) {
                v[t] = Ps[(lane + t * 32) * PS_STR + qi];
                mx = fmaxf(mx, v[t]);
            }
            #pragma unroll
            for (int o = 16; o > 0; o >>= 1) {
                mx = fmaxf(mx, __shfl_xor_sync(0xffffffffu, mx, o));
            }
            float sum = 0.0f;
            #pragma unroll
            for (int t = 0; t < 4; t++) {
                v[t] = expf(v[t] - mx);
                sum += v[t];
            }
            #pragma unroll
            for (int o = 16; o > 0; o >>= 1) {
                sum += __shfl_xor_sync(0xffffffffu, sum, o);
            }
            float inv = 1.0f / sum;
            #pragma unroll
            for (int t = 0; t < 4; t++) {
                Ps[(lane + t * 32) * PS_STR + qi] = v[t] * inv;
            }
        }
    }
    __syncthreads();

    for (int idx = tid; idx < 64 * 128; idx += 256) {
        int qi = idx >> 7;
        int slot = idx & 127;
        int i = i0 + qi;
        float val = 0.0f;
        if (i < WIN) {
            if (slot <= qi) {
                val = Ps[(slot + 64) * PS_STR + qi];
            }
        } else if (i >= S - WIN) {
            if (slot <= WIN) {
                val = Ps[(qi + slot) * PS_STR + qi];
            }
        }
        attn_w[((size_t)h * S + i) * 128 + slot] = val;
    }

    const int dk0 = tx * 4;
    float acc[4][4];
    #pragma unroll
    for (int i = 0; i < 4; i++) {
        #pragma unroll
        for (int j = 0; j < 4; j++) {
            acc[i][j] = 0.0f;
        }
    }
    #pragma unroll 4
    for (int kk = 0; kk < 128; kk++) {
        float4 p  = *(const float4*)&Ps[kk * PS_STR + qi0];
        float4 vv = *(const float4*)&Vs[kk * VS_STR + dk0];
        float pv[4] = {p.x, p.y, p.z, p.w};
        float vb[4] = {vv.x, vv.y, vv.z, vv.w};
        #pragma unroll
        for (int i = 0; i < 4; i++) {
            #pragma unroll
            for (int j = 0; j < 4; j++) {
                acc[i][j] = fmaf(pv[i], vb[j], acc[i][j]);
            }
        }
    }
    #pragma unroll
    for (int i = 0; i < 4; i++) {
        size_t base = (size_t)(i0 + qi0 + i) * DMODEL + h * DKH + dk0;
        __nv_bfloat16 hh[4];
        __nv_bfloat16 ll[4];
        #pragma unroll
        for (int j = 0; j < 4; j++) {
            float vv = acc[i][j];
            hh[j] = __float2bfloat16(vv);
            ll[j] = __float2bfloat16(vv - __bfloat162float(hh[j]));
        }
        *(__nv_bfloat162*)(g_AOh + base)     = __halves2bfloat162(hh[0], hh[1]);
        *(__nv_bfloat162*)(g_AOh + base + 2) = __halves2bfloat162(hh[2], hh[3]);
        *(__nv_bfloat162*)(g_AOl + base)     = __halves2bfloat162(ll[0], ll[1]);
        *(__nv_bfloat162*)(g_AOl + base + 2) = __halves2bfloat162(ll[2], ll[3]);
    }
}

// ---------------- launch ----------------
extern "C" void kernel_launch(void* const* d_in, const int* in_sizes, int n_in,
                              void* d_out, int out_size) {
    const float* q  = (const float*)d_in[0];
    const float* k  = (const float*)d_in[1];
    const float* v  = (const float*)d_in[2];
    const float* Wq = (const float*)d_in[3];
    const float* Wk = (const float*)d_in[4];
    const float* Wv = (const float*)d_in[5];
    const float* Wo = (const float*)d_in[6];
    const float* bo = (const float*)d_in[7];

    float* out    = (float*)d_out;
    float* attn_w = out + (size_t)SD;

    __nv_bfloat16* pxh;
    __nv_bfloat16* pxl;
    __nv_bfloat16* pwh;
    __nv_bfloat16* pwl;
    __nv_bfloat16* paoh;
    __nv_bfloat16* paol;
    float* pqkv;
    cudaGetSymbolAddress((void**)&pxh,  g_xh);
    cudaGetSymbolAddress((void**)&pxl,  g_xl);
    cudaGetSymbolAddress((void**)&pwh,  g_Wh);
    cudaGetSymbolAddress((void**)&pwl,  g_Wl);
    cudaGetSymbolAddress((void**)&pqkv, g_QKV);
    cudaGetSymbolAddress((void**)&paoh, g_AOh);
    cudaGetSymbolAddress((void**)&paol, g_AOl);

    const int SMEM = (64*QS_STR + 64*KS_STR + 128*VS_STR + 72) * (int)sizeof(float);
    cudaFuncSetAttribute(local_attn, cudaFuncAttributeMaxDynamicSharedMemorySize, SMEM);

    convert_split<<<4096, 256>>>(q, k, v, Wq, Wk, Wv, Wo);

    gemm128x64<<<dim3(DMODEL/64, S/128, 3), 256>>>(pxh, pxl, pwh, pwl, pqkv, nullptr);

    local_attn<<<dim3(S/64, NH), 256, SMEM>>>(pqkv, pqkv + SD, pqkv + 2*SD, attn_w);

    gemm128x64<<<dim3(DMODEL/64, S/128, 1), 256>>>(paoh, paol, pwh + 3*DD, pwl + 3*DD,
                                                   out, bo);
}

// round 5
// speedup vs baseline: 2.0113x; 1.0319x over previous
#include <cuda_runtime.h>
#include <cuda_bf16.h>
#include <cstdint>
#include <math.h>

#define S 2048
#define DMODEL 512
#define NH 8
#define DKH 64
#define WIN 64
#define NEGV -1000000000.0f
#define SD (S*DMODEL)
#define DD (DMODEL*DMODEL)

#define QS_STR 68
#define KS_STR 132
#define VS_STR 68
#define PS_STR 68

#define LDA 40

typedef unsigned int u32;

// ---------------- device scratch (allocation-free rule) ----------------
__device__ __nv_bfloat16 g_xh[3*SD];
__device__ __nv_bfloat16 g_xl[3*SD];
__device__ __nv_bfloat16 g_Wh[4*DD];
__device__ __nv_bfloat16 g_Wl[4*DD];
__device__ float g_QKV[3*SD];
__device__ __nv_bfloat16 g_AOh[SD];
__device__ __nv_bfloat16 g_AOl[SD];

// ---------------- fp32 -> bf16 hi/lo split ----------------
__global__ void __launch_bounds__(256) convert_split(
    const float* __restrict__ q, const float* __restrict__ k, const float* __restrict__ v,
    const float* __restrict__ Wq, const float* __restrict__ Wk,
    const float* __restrict__ Wv, const float* __restrict__ Wo)
{
    const int SD4 = SD/4;
    const int DD4 = DD/4;
    int idx = blockIdx.x * 256 + threadIdx.x;
    const float* src;
    __nv_bfloat16* dh;
    __nv_bfloat16* dl;
    if (idx < 3*SD4) {
        int r = idx / SD4;
        size_t e = (size_t)(idx - r*SD4) * 4;
        src = (r == 0 ? q : (r == 1 ? k : v)) + e;
        dh = g_xh + (size_t)r*SD + e;
        dl = g_xl + (size_t)r*SD + e;
    } else {
        int j = idx - 3*SD4;
        int r = j / DD4;
        size_t e = (size_t)(j - r*DD4) * 4;
        src = (r == 0 ? Wq : (r == 1 ? Wk : (r == 2 ? Wv : Wo))) + e;
        dh = g_Wh + (size_t)r*DD + e;
        dl = g_Wl + (size_t)r*DD + e;
    }
    float4 f = *(const float4*)src;
    __nv_bfloat16 h0 = __float2bfloat16(f.x);
    __nv_bfloat16 h1 = __float2bfloat16(f.y);
    __nv_bfloat16 h2 = __float2bfloat16(f.z);
    __nv_bfloat16 h3 = __float2bfloat16(f.w);
    __nv_bfloat16 l0 = __float2bfloat16(f.x - __bfloat162float(h0));
    __nv_bfloat16 l1 = __float2bfloat16(f.y - __bfloat162float(h1));
    __nv_bfloat16 l2 = __float2bfloat16(f.z - __bfloat162float(h2));
    __nv_bfloat16 l3 = __float2bfloat16(f.w - __bfloat162float(h3));
    *(__nv_bfloat162*)(dh)     = __halves2bfloat162(h0, h1);
    *(__nv_bfloat162*)(dh + 2) = __halves2bfloat162(h2, h3);
    *(__nv_bfloat162*)(dl)     = __halves2bfloat162(l0, l1);
    *(__nv_bfloat162*)(dl + 2) = __halves2bfloat162(l2, l3);
}

// ---------------- tensor-core GEMM helpers ----------------
__device__ __forceinline__ void ldsm4(u32* r, u32 a) {
    asm volatile("ldmatrix.sync.aligned.m8n8.x4.shared.b16 {%0,%1,%2,%3}, [%4];"
        : "=r"(r[0]), "=r"(r[1]), "=r"(r[2]), "=r"(r[3]) : "r"(a));
}
__device__ __forceinline__ void mma_bf16(float* c, const u32* a, const u32* b) {
    asm volatile("mma.sync.aligned.m16n8k16.row.col.f32.bf16.bf16.f32 "
        "{%0,%1,%2,%3},{%4,%5,%6,%7},{%8,%9},{%0,%1,%2,%3};"
        : "+f"(c[0]), "+f"(c[1]), "+f"(c[2]), "+f"(c[3])
        : "r"(a[0]), "r"(a[1]), "r"(a[2]), "r"(a[3]), "r"(b[0]), "r"(b[1]));
}
__device__ __forceinline__ void cp16(u32 dst, const void* src) {
    asm volatile("cp.async.cg.shared.global [%0], [%1], 16;" :: "r"(dst), "l"(src));
}
__device__ __forceinline__ void cp_commit() {
    asm volatile("cp.async.commit_group;");
}

// Per-stage byte sizes in dynamic smem
#define STG_A (128*LDA*2)
#define STG_W (64*LDA*2)
#define SMEM_GEMM (2*(2*STG_A + 2*STG_W))

// C[M,N] = A[M,K] @ W[N,K]^T (+bias). Split-bf16 3-term. Tile 128x64, BK=32.
// Double-buffered smem, cp.async pipeline.
__global__ void __launch_bounds__(256) gemm128x64(
    const __nv_bfloat16* __restrict__ Ah_, const __nv_bfloat16* __restrict__ Al_,
    const __nv_bfloat16* __restrict__ Wh_, const __nv_bfloat16* __restrict__ Wl_,
    float* __restrict__ C, const float* __restrict__ bias)
{
    extern __shared__ __align__(16) __nv_bfloat16 dsm[];

    const size_t za = (size_t)blockIdx.z * SD;
    const size_t zw = (size_t)blockIdx.z * DD;
    const int tid = threadIdx.x;
    const int m_base = blockIdx.y * 128;
    const int n_base = blockIdx.x * 64;

    const int a_row = tid >> 2;
    const int a_col = (tid & 3) * 8;

    const int lane = tid & 31;
    const int wid = tid >> 5;
    const int warp_m = wid >> 1;
    const int warp_n = wid & 1;
    const int lrow = (lane & 7) + ((lane >> 3) & 1) * 8;
    const int lcol = (lane >> 4) * 8;

    // smem region bases (bytes, shared address space)
    const u32 base = (u32)__cvta_generic_to_shared(dsm);
    const u32 bAh = base;
    const u32 bAl = base + 2*STG_A;
    const u32 bWh = base + 4*STG_A;
    const u32 bWl = base + 4*STG_A + 2*STG_W;

    const __nv_bfloat16* gA  = Ah_ + za + (size_t)(m_base + a_row) * DMODEL + a_col;
    const __nv_bfloat16* gL  = Al_ + za + (size_t)(m_base + a_row) * DMODEL + a_col;
    const __nv_bfloat16* gW  = Wh_ + zw + (size_t)(n_base + a_row) * DMODEL + a_col;
    const __nv_bfloat16* gWl = Wl_ + zw + (size_t)(n_base + a_row) * DMODEL + a_col;
    float* Cz = C + za;

    const u32 aoff = (u32)((a_row * LDA + a_col) * 2);
    const u32 woff = aoff;

    float acc[2][4][4];
    #pragma unroll
    for (int mi = 0; mi < 2; mi++) {
        #pragma unroll
        for (int ni = 0; ni < 4; ni++) {
            #pragma unroll
            for (int t = 0; t < 4; t++) {
                acc[mi][ni][t] = 0.0f;
            }
        }
    }

    // prologue: stage 0
    {
        cp16(bAh + aoff, gA);
        cp16(bAh + aoff + (u32)(64*LDA*2), gA + 64 * DMODEL);
        cp16(bAl + aoff, gL);
        cp16(bAl + aoff + (u32)(64*LDA*2), gL + 64 * DMODEL);
        cp16(bWh + woff, gW);
        cp16(bWl + woff, gWl);
        cp_commit();
    }

    for (int s = 0; s < 16; s++) {
        const u32 bufA = (u32)(s & 1) * STG_A;
        const u32 bufW = (u32)(s & 1) * STG_W;

        if (s < 15) {
            int k0 = (s + 1) * 32;
            u32 nbA = (u32)((s + 1) & 1) * STG_A;
            u32 nbW = (u32)((s + 1) & 1) * STG_W;
            cp16(bAh + nbA + aoff, gA + k0);
            cp16(bAh + nbA + aoff + (u32)(64*LDA*2), gA + k0 + 64 * DMODEL);
            cp16(bAl + nbA + aoff, gL + k0);
            cp16(bAl + nbA + aoff + (u32)(64*LDA*2), gL + k0 + 64 * DMODEL);
            cp16(bWh + nbW + woff, gW + k0);
            cp16(bWl + nbW + woff, gWl + k0);
            cp_commit();
            asm volatile("cp.async.wait_group 1;");
        } else {
            asm volatile("cp.async.wait_group 0;");
        }
        __syncthreads();

        #pragma unroll
        for (int kb = 0; kb < 32; kb += 16) {
            u32 ah[2][4];
            u32 al[2][4];
            u32 bh[4][2];
            u32 bl[4][2];
            #pragma unroll
            for (int mi = 0; mi < 2; mi++) {
                u32 off = bufA + (u32)(((warp_m * 32 + mi * 16 + lrow) * LDA + kb + lcol) * 2);
                ldsm4(ah[mi], bAh + off);
                ldsm4(al[mi], bAl + off);
            }
            #pragma unroll
            for (int g2 = 0; g2 < 2; g2++) {
                u32 off = bufW + (u32)(((warp_n * 32 + g2 * 16 + lrow) * LDA + kb + lcol) * 2);
                u32 r0[4];
                ldsm4(r0, bWh + off);
                bh[g2*2][0]   = r0[0];
                bh[g2*2+1][0] = r0[1];
                bh[g2*2][1]   = r0[2];
                bh[g2*2+1][1] = r0[3];
                u32 r1[4];
                ldsm4(r1, bWl + off);
                bl[g2*2][0]   = r1[0];
                bl[g2*2+1][0] = r1[1];
                bl[g2*2][1]   = r1[2];
                bl[g2*2+1][1] = r1[3];
            }
            #pragma unroll
            for (int mi = 0; mi < 2; mi++) {
                #pragma unroll
                for (int ni = 0; ni < 4; ni++) {
                    mma_bf16(acc[mi][ni], ah[mi], bh[ni]);
                    mma_bf16(acc[mi][ni], ah[mi], bl[ni]);
                    mma_bf16(acc[mi][ni], al[mi], bh[ni]);
                }
            }
        }
        __syncthreads();
    }

    const int qr = lane >> 2;
    const int qc = (lane & 3) * 2;
    #pragma unroll
    for (int mi = 0; mi < 2; mi++) {
        int m0 = m_base + warp_m * 32 + mi * 16 + qr;
        #pragma unroll
        for (int ni = 0; ni < 4; ni++) {
            int n = n_base + warp_n * 32 + ni * 8 + qc;
            float b0 = 0.0f;
            float b1 = 0.0f;
            if (bias) {
                b0 = bias[n];
                b1 = bias[n + 1];
            }
            float2 v0 = make_float2(acc[mi][ni][0] + b0, acc[mi][ni][1] + b1);
            float2 v1 = make_float2(acc[mi][ni][2] + b0, acc[mi][ni][3] + b1);
            *(float2*)(Cz + (size_t)m0 * DMODEL + n) = v0;
            *(float2*)(Cz + (size_t)(m0 + 8) * DMODEL + n) = v1;
        }
    }
}

// ---------------- windowed attention ----------------
__global__ void __launch_bounds__(256) local_attn(
    const float* __restrict__ Q, const float* __restrict__ K,
    const float* __restrict__ V, float* __restrict__ attn_w)
{
    extern __shared__ __align__(16) float sm[];
    float* Qs = sm;
    float* Ks = sm + 64*QS_STR;
    float* Vs = sm + 64*QS_STR + 64*KS_STR;
    float* bias_s = Vs + 128*VS_STR;
    float* Ps = sm;   // aliases Qs+Ks after scores move to registers

    const int h  = blockIdx.y;
    const int i0 = blockIdx.x * 64;
    const int tid = threadIdx.x;

    if (tid <= WIN) {
        bias_s[tid] = 0.1f * expf(-0.1f * (float)(WIN - tid));
    }

    for (int idx = tid; idx < 64 * 64; idx += 256) {
        int qi = idx >> 6;
        int d  = idx & 63;
        Qs[d * QS_STR + qi] = Q[(size_t)(i0 + qi) * DMODEL + h * DKH + d];
    }
    for (int idx = tid; idx < 128 * 64; idx += 256) {
        int kk = idx >> 6;
        int d  = idx & 63;
        int j = i0 - 64 + kk;
        int jc = (j < 0) ? 0 : j;
        Ks[d * KS_STR + kk] = K[(size_t)jc * DMODEL + h * DKH + d];
        Vs[kk * VS_STR + d] = V[(size_t)jc * DMODEL + h * DKH + d];
    }
    __syncthreads();

    const int tx = tid & 15;
    const int ty = tid >> 4;
    const int qi0 = ty * 4;
    const int kk0 = tx * 8;

    float sc[4][8];
    #pragma unroll
    for (int i = 0; i < 4; i++) {
        #pragma unroll
        for (int j = 0; j < 8; j++) {
            sc[i][j] = 0.0f;
        }
    }
    #pragma unroll 8
    for (int d = 0; d < 64; d++) {
        float4 a  = *(const float4*)&Qs[d * QS_STR + qi0];
        float4 b0 = *(const float4*)&Ks[d * KS_STR + kk0];
        float4 b1 = *(const float4*)&Ks[d * KS_STR + kk0 + 4];
        float av[4] = {a.x, a.y, a.z, a.w};
        float bv[8] = {b0.x, b0.y, b0.z, b0.w, b1.x, b1.y, b1.z, b1.w};
        #pragma unroll
        for (int i = 0; i < 4; i++) {
            #pragma unroll
            for (int j = 0; j < 8; j++) {
                sc[i][j] = fmaf(av[i], bv[j], sc[i][j]);
            }
        }
    }
    __syncthreads();   // scores in regs; safe to overwrite Qs/Ks with Ps

    #pragma unroll
    for (int i = 0; i < 4; i++) {
        #pragma unroll
        for (int j = 0; j < 8; j++) {
            int qi = qi0 + i;
            int kk = kk0 + j;
            int r  = kk - qi;
            int jg = i0 - 64 + kk;
            float val = NEGV;
            if (r >= 0 && r <= WIN && jg >= 0) {
                val = sc[i][j] * 0.125f + bias_s[r];
            }
            Ps[kk * PS_STR + qi] = val;
        }
    }
    __syncthreads();

    {
        const int warp = tid >> 5;
        const int lane = tid & 31;
        for (int rr = 0; rr < 8; rr++) {
            int qi = warp * 8 + rr;
            float v[4];
            float mx = -3.4e38f;
            #pragma unroll
            for (int t = 0; t < 4; t++) {
                v[t] = Ps[(lane + t * 32) * PS_STR + qi];
                mx = fmaxf(mx, v[t]);
            }
            #pragma unroll
            for (int o = 16; o > 0; o >>= 1) {
                mx = fmaxf(mx, __shfl_xor_sync(0xffffffffu, mx, o));
            }
            float sum = 0.0f;
            #pragma unroll
            for (int t = 0; t < 4; t++) {
                v[t] = expf(v[t] - mx);
                sum += v[t];
            }
            #pragma unroll
            for (int o = 16; o > 0; o >>= 1) {
                sum += __shfl_xor_sync(0xffffffffu, sum, o);
            }
            float inv = 1.0f / sum;
            #pragma unroll
            for (int t = 0; t < 4; t++) {
                Ps[(lane + t * 32) * PS_STR + qi] = v[t] * inv;
            }
        }
    }
    __syncthreads();

    for (int idx = tid; idx < 64 * 128; idx += 256) {
        int qi = idx >> 7;
        int slot = idx & 127;
        int i = i0 + qi;
        float val = 0.0f;
        if (i < WIN) {
            if (slot <= qi) {
                val = Ps[(slot + 64) * PS_STR + qi];
            }
        } else if (i >= S - WIN) {
            if (slot <= WIN) {
                val = Ps[(qi + slot) * PS_STR + qi];
            }
        }
        attn_w[((size_t)h * S + i) * 128 + slot] = val;
    }

    const int dk0 = tx * 4;
    float acc[4][4];
    #pragma unroll
    for (int i = 0; i < 4; i++) {
        #pragma unroll
        for (int j = 0; j < 4; j++) {
            acc[i][j] = 0.0f;
        }
    }
    #pragma unroll 4
    for (int kk = 0; kk < 128; kk++) {
        float4 p  = *(const float4*)&Ps[kk * PS_STR + qi0];
        float4 vv = *(const float4*)&Vs[kk * VS_STR + dk0];
        float pv[4] = {p.x, p.y, p.z, p.w};
        float vb[4] = {vv.x, vv.y, vv.z, vv.w};
        #pragma unroll
        for (int i = 0; i < 4; i++) {
            #pragma unroll
            for (int j = 0; j < 4; j++) {
                acc[i][j] = fmaf(pv[i], vb[j], acc[i][j]);
            }
        }
    }
    #pragma unroll
    for (int i = 0; i < 4; i++) {
        size_t base = (size_t)(i0 + qi0 + i) * DMODEL + h * DKH + dk0;
        __nv_bfloat16 hh[4];
        __nv_bfloat16 ll[4];
        #pragma unroll
        for (int j = 0; j < 4; j++) {
            float vv = acc[i][j];
            hh[j] = __float2bfloat16(vv);
            ll[j] = __float2bfloat16(vv - __bfloat162float(hh[j]));
        }
        *(__nv_bfloat162*)(g_AOh + base)     = __halves2bfloat162(hh[0], hh[1]);
        *(__nv_bfloat162*)(g_AOh + base + 2) = __halves2bfloat162(hh[2], hh[3]);
        *(__nv_bfloat162*)(g_AOl + base)     = __halves2bfloat162(ll[0], ll[1]);
        *(__nv_bfloat162*)(g_AOl + base + 2) = __halves2bfloat162(ll[2], ll[3]);
    }
}

// ---------------- launch ----------------
extern "C" void kernel_launch(void* const* d_in, const int* in_sizes, int n_in,
                              void* d_out, int out_size) {
    const float* q  = (const float*)d_in[0];
    const float* k  = (const float*)d_in[1];
    const float* v  = (const float*)d_in[2];
    const float* Wq = (const float*)d_in[3];
    const float* Wk = (const float*)d_in[4];
    const float* Wv = (const float*)d_in[5];
    const float* Wo = (const float*)d_in[6];
    const float* bo = (const float*)d_in[7];

    float* out    = (float*)d_out;
    float* attn_w = out + (size_t)SD;

    __nv_bfloat16* pxh;
    __nv_bfloat16* pxl;
    __nv_bfloat16* pwh;
    __nv_bfloat16* pwl;
    __nv_bfloat16* paoh;
    __nv_bfloat16* paol;
    float* pqkv;
    cudaGetSymbolAddress((void**)&pxh,  g_xh);
    cudaGetSymbolAddress((void**)&pxl,  g_xl);
    cudaGetSymbolAddress((void**)&pwh,  g_Wh);
    cudaGetSymbolAddress((void**)&pwl,  g_Wl);
    cudaGetSymbolAddress((void**)&pqkv, g_QKV);
    cudaGetSymbolAddress((void**)&paoh, g_AOh);
    cudaGetSymbolAddress((void**)&paol, g_AOl);

    const int SMEM_ATTN = (64*QS_STR + 64*KS_STR + 128*VS_STR + 72) * (int)sizeof(float);
    cudaFuncSetAttribute(local_attn, cudaFuncAttributeMaxDynamicSharedMemorySize, SMEM_ATTN);
    cudaFuncSetAttribute(gemm128x64, cudaFuncAttributeMaxDynamicSharedMemorySize, SMEM_GEMM);

    convert_split<<<4096, 256>>>(q, k, v, Wq, Wk, Wv, Wo);

    gemm128x64<<<dim3(DMODEL/64, S/128, 3), 256, SMEM_GEMM>>>(pxh, pxl, pwh, pwl, pqkv, nullptr);

    local_attn<<<dim3(S/64, NH), 256, SMEM_ATTN>>>(pqkv, pqkv + SD, pqkv + 2*SD, attn_w);

    gemm128x64<<<dim3(DMODEL/64, S/128, 1), 256, SMEM_GEMM>>>(paoh, paol, pwh + 3*DD, pwl + 3*DD,
                                                              out, bo);
}